// round 13
// baseline (speedup 1.0000x reference)
#include <cuda_runtime.h>
#include <cuda_fp16.h>
#include <cstdint>

#define H     128
#define RDIM  6
#define FEAT  390
#define NSM   152
#define LDR   136     // B tile row stride (fp16)
#define LDH   136     // fp16 staging row stride (halfs)
// per-warp staging slab: 8 rows x LDH halfs = 2176 B; 8 warps = 17408 B

// ---- device scratch ----
__device__ __align__(16) float  g_part[8 * 96 * H];
__device__ __align__(16) __half g_AtabH[96 * 3 * H];   // fp16 combo tables
__device__ __align__(16) __half g_BtabH[96 * 3 * H];
__device__ int                  g_combo[65536];
__device__ __align__(16) __half g_W3h[H * H];          // fp16(W3), n-major [n][k]
__device__ unsigned             g_tileCtr;

__device__ __forceinline__ float fast_silu(float x) {
    float t, h = 0.5f * x;
    asm("tanh.approx.f32 %0, %1;" : "=f"(t) : "f"(h));
    return h + h * t;
}
// silu on two fp32 values computed in fp16x2, returns packed fp16x2
__device__ __forceinline__ uint32_t silu2h(float v0, float v1) {
    __half2 hm = __floats2half2_rn(0.5f * v0, 0.5f * v1);
    uint32_t hu = *(uint32_t*)&hm, tu;
    asm("tanh.approx.f16x2 %0, %1;" : "=r"(tu) : "r"(hu));
    __half2 th = *(__half2*)&tu;
    __half2 r = __hfma2(hm, th, hm);       // h + h*t = x*sigmoid(x)
    return *(uint32_t*)&r;
}
__device__ __forceinline__ uint32_t smem_u32(const void* p) {
    uint32_t a;
    asm("{ .reg .u64 t; cvta.to.shared.u64 t, %1; cvt.u32.u64 %0, t; }" : "=r"(a) : "l"(p));
    return a;
}
__device__ __forceinline__ void ldsm4(uint32_t* r, uint32_t addr) {
    asm volatile("ldmatrix.sync.aligned.m8n8.x4.shared.b16 {%0,%1,%2,%3}, [%4];"
                 : "=r"(r[0]), "=r"(r[1]), "=r"(r[2]), "=r"(r[3]) : "r"(addr));
}
__device__ __forceinline__ void mma16816(float* c, const uint32_t* a, const uint32_t* b) {
    asm volatile("mma.sync.aligned.m16n8k16.row.col.f32.f16.f16.f32 "
                 "{%0,%1,%2,%3}, {%4,%5,%6,%7}, {%8,%9}, {%0,%1,%2,%3};"
                 : "+f"(c[0]), "+f"(c[1]), "+f"(c[2]), "+f"(c[3])
                 : "r"(a[0]), "r"(a[1]), "r"(a[2]), "r"(a[3]), "r"(b[0]), "r"(b[1]));
}
__device__ __forceinline__ int grab_tile() {
    unsigned v = 0;
    if ((threadIdx.x & 31) == 0) v = atomicAdd(&g_tileCtr, 1u);
    return (int)__shfl_sync(0xffffffffu, v, 0);
}

// ---------------------------------------------------------------------------
// Prologue 1 (merged): GEMV partials (192 blocks, 4 atoms each) | combo | W3
// ---------------------------------------------------------------------------
__global__ void prologue1(const int* __restrict__ x, const int* __restrict__ s,
                          const float* __restrict__ emb_w, const float* __restrict__ lin_w,
                          int N, int nCombo, int nEmb)
{
    const int b = blockIdx.x, tid = threadIdx.x;
    if (b < 192) {
        __shared__ float sw[128 * 33];
        __shared__ float se[4 * 32];
        const int c = b / 24, g = b % 24;
        const int base = (c < 4) ? c * 32 : 131 + (c - 4) * 32;
        const int ec = (c & 3) * 32;
        if (tid < 128) {
            int a = g * 4 + (tid >> 5), k = tid & 31;
            se[tid] = (a < nEmb) ? emb_w[a * H + ec + k] : 0.f;
        }
        for (int idx = tid; idx < 128 * 32; idx += 256) {
            int r = idx >> 5, k = idx & 31;
            sw[r * 33 + k] = lin_w[(size_t)r * FEAT + base + k];
        }
        __syncthreads();
        if (tid < 128) {
#pragma unroll
            for (int u = 0; u < 4; u++) {
                int a = g * 4 + u;
                if (a < nEmb) {
                    float acc = 0.f;
#pragma unroll
                    for (int k = 0; k < 32; k++) acc += sw[tid * 33 + k] * se[u * 32 + k];
                    g_part[(c * 96 + a) * H + tid] = acc;
                }
            }
        }
    } else if (b < 192 + nCombo) {
        int n = (b - 192) * 256 + tid;
        if (n < N) g_combo[n] = x[n] * 3 + s[n];
    } else {
        int idx = (b - 192 - nCombo) * 256 + tid;
        if (idx < H * H) {
            int n = idx >> 7, k = idx & 127;
            g_W3h[idx] = __float2half_rn(lin_w[(size_t)n * FEAT + (2 * H + 6) + k]);
        }
    }
}

// ---------------------------------------------------------------------------
// Prologue 2: combine -> fp16 tables (285 blocks); also resets tile counter
// ---------------------------------------------------------------------------
__global__ void prologue2(const float* __restrict__ spin_w, const float* __restrict__ spin_b,
                          const float* __restrict__ lin_w, const float* __restrict__ lin_b)
{
    const int b = blockIdx.x, n = threadIdx.x;
    if (b == 0 && n == 0) g_tileCtr = 0u;
    const int a = b / 3, sc = b % 3;
    float A = 0.f, B = 0.f;
#pragma unroll
    for (int c = 0; c < 4; c++) A += g_part[(c * 96 + a) * H + n];
#pragma unroll
    for (int c = 4; c < 8; c++) B += g_part[(c * 96 + a) * H + n];
    const float* wrow = lin_w + (size_t)n * FEAT;
    float sf0 = spin_w[0 * 3 + sc] + spin_b[0];
    float sf1 = spin_w[1 * 3 + sc] + spin_b[1];
    float sf2 = spin_w[2 * 3 + sc] + spin_b[2];
    g_AtabH[b * H + n] = __float2half_rn(A + wrow[128] * sf0 + wrow[129] * sf1 + wrow[130] * sf2 + lin_b[n]);
    g_BtabH[b * H + n] = __float2half_rn(B + wrow[259] * sf0 + wrow[260] * sf1 + wrow[261] * sf2);
}

// no-op launch-window shifter so ncu (-s 5 -c 1) lands on edge_kernel
__global__ void knock() {}

// ---------------------------------------------------------------------------
// Persistent edge kernel: warp-independent 16-edge x 128-col tiles,
// work stealing, fp16 MMA, float4 weight fetch, fp16 staging.
// dyn smem: sBh(34816) | swh(17408) = 52224 B
// ---------------------------------------------------------------------------
__global__ void __launch_bounds__(256, 2)
edge_kernel(const float* __restrict__ rbf,
            const int*   __restrict__ ii,
            const int*   __restrict__ jj,
            const float* __restrict__ rbf_w,
            const float* __restrict__ rbf_b,
            float*       __restrict__ out,
            int E)
{
    extern __shared__ __align__(16) char smem[];
    __half* sBh  = (__half*)(smem);
    __half* sWst = (__half*)(smem + 34816);

    __shared__ float4 s_rwP[H * 2];   // per k: {bias, w0,w1,w2}, {w3,w4,w5,0}

    const int tid = threadIdx.x, w = tid >> 5, lane = tid & 31;

    if (tid < H) {
        const float* wr = rbf_w + tid * RDIM;
        s_rwP[tid * 2]     = make_float4(rbf_b[tid], wr[0], wr[1], wr[2]);
        s_rwP[tid * 2 + 1] = make_float4(wr[3], wr[4], wr[5], 0.f);
    }
    for (int idx = tid; idx < H * H; idx += 256) {
        int n = idx >> 7, k = idx & 127;
        sBh[n * LDR + k] = g_W3h[idx];
    }
    __syncthreads();

    const uint32_t bBase = smem_u32(sBh)
        + (uint32_t)((((lane >> 4) & 1) * 8 + (lane & 7)) * LDR + ((lane >> 3) & 1) * 8) * 2u;

    __half* swh_ = sWst + w * (8 * LDH);

    const int r0 = lane >> 2, r1 = r0 + 8;
    const int c0 = (lane & 3) * 2;
    const int el = lane & 15;

    const int ntiles = (E + 15) >> 4;

    // ---- grab + prefetch first tile
    int t = grab_tile();
    float rr0[RDIM], rr1[RDIM];
    int myc = 0;
    if (t < ntiles) {
        const int eb = t * 16;
        const float* p0 = rbf + (size_t)min(eb + r0, E - 1) * RDIM;
        const float* p1 = rbf + (size_t)min(eb + r1, E - 1) * RDIM;
#pragma unroll
        for (int q = 0; q < RDIM; q += 2) {
            float2 u = *(const float2*)(p0 + q); rr0[q] = u.x; rr0[q + 1] = u.y;
            float2 v = *(const float2*)(p1 + q); rr1[q] = v.x; rr1[q + 1] = v.y;
        }
        int le = min(eb + el, E - 1);
        myc = g_combo[(lane < 16) ? ii[le] : jj[le]];
    }

    while (t < ntiles) {
        const int eb = t * 16;
        const int tn = grab_tile();    // latency hidden under this tile

        float c[16][4];
#pragma unroll
        for (int f = 0; f < 16; f++) { c[f][0] = 0.f; c[f][1] = 0.f; c[f][2] = 0.f; c[f][3] = 0.f; }

#pragma unroll
        for (int ks = 0; ks < 8; ks++) {
            // ---- A fragments in registers: float4 weight rows, fp16x2 silu
            const int ka = ks * 16 + c0;
            float m0[4], m1[4];    // [edge][kk], kk -> k = ka + (kk>>1)*8 + (kk&1)
#pragma unroll
            for (int kk = 0; kk < 4; kk++) {
                const int kr = ka + (kk >> 1) * 8 + (kk & 1);
                float4 wA = s_rwP[kr * 2];
                float4 wB = s_rwP[kr * 2 + 1];
                m0[kk] = wA.x + rr0[0] * wA.y + rr0[1] * wA.z + rr0[2] * wA.w
                              + rr0[3] * wB.x + rr0[4] * wB.y + rr0[5] * wB.z;
                m1[kk] = wA.x + rr1[0] * wA.y + rr1[1] * wA.z + rr1[2] * wA.w
                              + rr1[3] * wB.x + rr1[4] * wB.y + rr1[5] * wB.z;
            }
            uint32_t a[4];
            a[0] = silu2h(m0[0], m0[1]);
            a[1] = silu2h(m1[0], m1[1]);
            a[2] = silu2h(m0[2], m0[3]);
            a[3] = silu2h(m1[2], m1[3]);

            const uint32_t koff = (uint32_t)ks * 32u;
#pragma unroll
            for (int fp = 0; fp < 8; fp++) {
                uint32_t bh[4];
                ldsm4(bh, bBase + (uint32_t)fp * (16u * LDR * 2u) + koff);
                mma16816(c[2 * fp],     a, bh);
                mma16816(c[2 * fp + 1], a, bh + 2);
            }
        }

        // ---- prefetch next tile directly into rr; epilogue hides it
        int nmyc = 0;
        if (tn < ntiles) {
            const int ebn = tn * 16;
            const float* p0 = rbf + (size_t)min(ebn + r0, E - 1) * RDIM;
            const float* p1 = rbf + (size_t)min(ebn + r1, E - 1) * RDIM;
#pragma unroll
            for (int q = 0; q < RDIM; q += 2) {
                float2 u = *(const float2*)(p0 + q); rr0[q] = u.x; rr0[q + 1] = u.y;
                float2 v = *(const float2*)(p1 + q); rr1[q] = v.x; rr1[q + 1] = v.y;
            }
            int le = min(ebn + el, E - 1);
            nmyc = g_combo[(lane < 16) ? ii[le] : jj[le]];
        }

        // ---- epilogue: two 8-edge slabs, fp16 staging, coalesced out
#pragma unroll
        for (int p = 0; p < 2; p++) {
#pragma unroll
            for (int f = 0; f < 16; f++) {
                const int lc = f * 8 + c0;   // max 126 < LDH
                __half2 hv = p ? __floats2half2_rn(c[f][2], c[f][3])
                               : __floats2half2_rn(c[f][0], c[f][1]);
                *(__half2*)(swh_ + r0 * LDH + lc) = hv;
            }
            __syncwarp();
            const int colb = lane * 4;
#pragma unroll
            for (int e = 0; e < 8; e++) {
                const int ge = eb + p * 8 + e;
                const int ci = __shfl_sync(0xffffffffu, myc, p * 8 + e);
                const int cj = __shfl_sync(0xffffffffu, myc, 16 + p * 8 + e);
                uint2 acr = *(const uint2*)(swh_ + e * LDH + colb);
                uint2 ar  = *(const uint2*)(g_AtabH + ci * H + colb);
                uint2 br  = *(const uint2*)(g_BtabH + cj * H + colb);
                __half2 s01 = __hadd2(__hadd2(*(__half2*)&acr.x, *(__half2*)&ar.x), *(__half2*)&br.x);
                __half2 s23 = __hadd2(__hadd2(*(__half2*)&acr.y, *(__half2*)&ar.y), *(__half2*)&br.y);
                float2 f01 = __half22float2(s01), f23 = __half22float2(s23);
                float4 o;
                o.x = fast_silu(f01.x);
                o.y = fast_silu(f01.y);
                o.z = fast_silu(f23.x);
                o.w = fast_silu(f23.y);
                if (ge < E) __stcs((float4*)(out + (size_t)ge * H + colb), o);
            }
            __syncwarp();
        }

        myc = nmyc;
        t = tn;
    }
}

// ---------------------------------------------------------------------------
extern "C" void kernel_launch(void* const* d_in, const int* in_sizes, int n_in,
                              void* d_out, int out_size)
{
    const int*   x      = (const int*)  d_in[0];
    const int*   s      = (const int*)  d_in[1];
    const float* rbf    = (const float*)d_in[2];
    const int*   ii     = (const int*)  d_in[3];
    const int*   jj     = (const int*)  d_in[4];
    const float* emb_w  = (const float*)d_in[5];
    const float* spin_w = (const float*)d_in[6];
    const float* spin_b = (const float*)d_in[7];
    const float* rbf_w  = (const float*)d_in[8];
    const float* rbf_b  = (const float*)d_in[9];
    const float* lin_w  = (const float*)d_in[10];
    const float* lin_b  = (const float*)d_in[11];
    float* out = (float*)d_out;

    int N    = in_sizes[0];
    int E    = in_sizes[3];
    int nEmb = in_sizes[5] / H;     // 95

    int nCombo = (N + 255) / 256;
    int nSplit = (H * H + 255) / 256;
    prologue1<<<192 + nCombo + nSplit, 256>>>(x, s, emb_w, lin_w, N, nCombo, nEmb);
    prologue2<<<285, 128>>>(spin_w, spin_b, lin_w, lin_b);
    knock<<<1, 32>>>();

    cudaFuncSetAttribute(edge_kernel, cudaFuncAttributeMaxDynamicSharedMemorySize, 52224);
    edge_kernel<<<NSM * 2, 256, 52224>>>(rbf, ii, jj, rbf_w, rbf_b, out, E);
}

// round 14
// speedup vs baseline: 1.2812x; 1.2812x over previous
#include <cuda_runtime.h>
#include <cuda_fp16.h>
#include <cstdint>

#define H     128
#define RDIM  6
#define FEAT  390
#define NSM   152
#define LDR   136     // B tile row stride (fp16)
#define LDW2  132     // fp32 staging row stride (floats)
// per-warp staging slab: 8 rows x LDW2 floats = 4224 B; 8 warps = 33792 B

// ---- device scratch ----
__device__ __align__(16) float  g_part[8 * 96 * H];
__device__ __align__(16) __half g_AtabH[96 * 3 * H];   // fp16 combo tables
__device__ __align__(16) __half g_BtabH[96 * 3 * H];
__device__ int                  g_combo[65536];
__device__ __align__(16) __half g_W3h[H * H];          // fp16(W3), n-major [n][k]
__device__ unsigned             g_tileCtr;

__device__ __forceinline__ float fast_silu(float x) {
    float t, h = 0.5f * x;
    asm("tanh.approx.f32 %0, %1;" : "=f"(t) : "f"(h));
    return h + h * t;
}
__device__ __forceinline__ uint32_t smem_u32(const void* p) {
    uint32_t a;
    asm("{ .reg .u64 t; cvta.to.shared.u64 t, %1; cvt.u32.u64 %0, t; }" : "=r"(a) : "l"(p));
    return a;
}
__device__ __forceinline__ void ldsm4(uint32_t* r, uint32_t addr) {
    asm volatile("ldmatrix.sync.aligned.m8n8.x4.shared.b16 {%0,%1,%2,%3}, [%4];"
                 : "=r"(r[0]), "=r"(r[1]), "=r"(r[2]), "=r"(r[3]) : "r"(addr));
}
__device__ __forceinline__ void mma16816(float* c, const uint32_t* a, const uint32_t* b) {
    asm volatile("mma.sync.aligned.m16n8k16.row.col.f32.f16.f16.f32 "
                 "{%0,%1,%2,%3}, {%4,%5,%6,%7}, {%8,%9}, {%0,%1,%2,%3};"
                 : "+f"(c[0]), "+f"(c[1]), "+f"(c[2]), "+f"(c[3])
                 : "r"(a[0]), "r"(a[1]), "r"(a[2]), "r"(a[3]), "r"(b[0]), "r"(b[1]));
}
// m16n8k8: pre-activation GEMM (A: edges x rbf-dims, B: rbfW col-strip)
__device__ __forceinline__ void mma1688(float* c, uint32_t a0, uint32_t a1, uint32_t b0) {
    asm volatile("mma.sync.aligned.m16n8k8.row.col.f32.f16.f16.f32 "
                 "{%0,%1,%2,%3}, {%4,%5}, {%6}, {%0,%1,%2,%3};"
                 : "+f"(c[0]), "+f"(c[1]), "+f"(c[2]), "+f"(c[3])
                 : "r"(a0), "r"(a1), "r"(b0));
}
__device__ __forceinline__ uint32_t pack2h(float v0, float v1) {
    __half h0 = __float2half_rn(v0), h1 = __float2half_rn(v1);
    return (uint32_t)__half_as_ushort(h0) | ((uint32_t)__half_as_ushort(h1) << 16);
}
__device__ __forceinline__ int grab_tile() {
    unsigned v = 0;
    if ((threadIdx.x & 31) == 0) v = atomicAdd(&g_tileCtr, 1u);
    return (int)__shfl_sync(0xffffffffu, v, 0);
}

// ---------------------------------------------------------------------------
// Prologue 1 (merged): GEMV partials (192 blocks, 4 atoms each) | combo | W3
// ---------------------------------------------------------------------------
__global__ void prologue1(const int* __restrict__ x, const int* __restrict__ s,
                          const float* __restrict__ emb_w, const float* __restrict__ lin_w,
                          int N, int nCombo, int nEmb)
{
    const int b = blockIdx.x, tid = threadIdx.x;
    if (b < 192) {
        __shared__ float sw[128 * 33];
        __shared__ float se[4 * 32];
        const int c = b / 24, g = b % 24;
        const int base = (c < 4) ? c * 32 : 131 + (c - 4) * 32;
        const int ec = (c & 3) * 32;
        if (tid < 128) {
            int a = g * 4 + (tid >> 5), k = tid & 31;
            se[tid] = (a < nEmb) ? emb_w[a * H + ec + k] : 0.f;
        }
        for (int idx = tid; idx < 128 * 32; idx += 256) {
            int r = idx >> 5, k = idx & 31;
            sw[r * 33 + k] = lin_w[(size_t)r * FEAT + base + k];
        }
        __syncthreads();
        if (tid < 128) {
#pragma unroll
            for (int u = 0; u < 4; u++) {
                int a = g * 4 + u;
                if (a < nEmb) {
                    float acc = 0.f;
#pragma unroll
                    for (int k = 0; k < 32; k++) acc += sw[tid * 33 + k] * se[u * 32 + k];
                    g_part[(c * 96 + a) * H + tid] = acc;
                }
            }
        }
    } else if (b < 192 + nCombo) {
        int n = (b - 192) * 256 + tid;
        if (n < N) g_combo[n] = x[n] * 3 + s[n];
    } else {
        int idx = (b - 192 - nCombo) * 256 + tid;
        if (idx < H * H) {
            int n = idx >> 7, k = idx & 127;
            g_W3h[idx] = __float2half_rn(lin_w[(size_t)n * FEAT + (2 * H + 6) + k]);
        }
    }
}

// ---------------------------------------------------------------------------
// Prologue 2: combine -> fp16 tables (285 blocks); also resets tile counter
// ---------------------------------------------------------------------------
__global__ void prologue2(const float* __restrict__ spin_w, const float* __restrict__ spin_b,
                          const float* __restrict__ lin_w, const float* __restrict__ lin_b)
{
    const int b = blockIdx.x, n = threadIdx.x;
    if (b == 0 && n == 0) g_tileCtr = 0u;
    const int a = b / 3, sc = b % 3;
    float A = 0.f, B = 0.f;
#pragma unroll
    for (int c = 0; c < 4; c++) A += g_part[(c * 96 + a) * H + n];
#pragma unroll
    for (int c = 4; c < 8; c++) B += g_part[(c * 96 + a) * H + n];
    const float* wrow = lin_w + (size_t)n * FEAT;
    float sf0 = spin_w[0 * 3 + sc] + spin_b[0];
    float sf1 = spin_w[1 * 3 + sc] + spin_b[1];
    float sf2 = spin_w[2 * 3 + sc] + spin_b[2];
    g_AtabH[b * H + n] = __float2half_rn(A + wrow[128] * sf0 + wrow[129] * sf1 + wrow[130] * sf2 + lin_b[n]);
    g_BtabH[b * H + n] = __float2half_rn(B + wrow[259] * sf0 + wrow[260] * sf1 + wrow[261] * sf2);
}

// no-op launch-window shifter so ncu (-s 5 -c 1) lands on edge_kernel
__global__ void knock() {}

// ---------------------------------------------------------------------------
// Persistent edge kernel: warp-independent 16-edge x 128-col tiles.
// A-gen done BY TENSOR CORE (m16n8k8, bias folded as 7th rbf dim) -> acc
// layout == main-MMA A-frag layout. Zero weight-LDS in the loop.
// dyn smem: sBh(34816) | sWst(33792) = 68608 B
// ---------------------------------------------------------------------------
__global__ void __launch_bounds__(256, 2)
edge_kernel(const float* __restrict__ rbf,
            const int*   __restrict__ ii,
            const int*   __restrict__ jj,
            const float* __restrict__ rbf_w,
            const float* __restrict__ rbf_b,
            float*       __restrict__ out,
            int E)
{
    extern __shared__ __align__(16) char smem[];
    __half* sBh  = (__half*)(smem);
    float*  sWst = (float*)(smem + 34816);

    const int tid = threadIdx.x, w = tid >> 5, lane = tid & 31;

    for (int idx = tid; idx < H * H; idx += 256) {
        int n = idx >> 7, k = idx & 127;
        sBh[n * LDR + k] = g_W3h[idx];
    }
    __syncthreads();

    const uint32_t bBase = smem_u32(sBh)
        + (uint32_t)((((lane >> 4) & 1) * 8 + (lane & 7)) * LDR + ((lane >> 3) & 1) * 8) * 2u;

    float* sw_ = sWst + w * (8 * LDW2);

    const int r0 = lane >> 2, r1 = r0 + 8;
    const int c0 = (lane & 3) * 2;
    const int el = lane & 15;
    const int kd = (lane & 3) * 2;       // this lane's rbf-dim pair for pre-MMA

    // ---- rbfW B-fragments for the pre-activation MMA, loaded ONCE.
    // bpre[ks][g]: (kdim=kd,kd+1 ; col = ks*16 + g*8 + (lane>>2)); kd==6 -> (bias, 0)
    uint32_t bpre[8][2];
#pragma unroll
    for (int ks = 0; ks < 8; ks++)
#pragma unroll
        for (int g = 0; g < 2; g++) {
            int col = ks * 16 + g * 8 + (lane >> 2);
            float v0, v1;
            if (kd < RDIM) { v0 = rbf_w[col * RDIM + kd]; v1 = rbf_w[col * RDIM + kd + 1]; }
            else           { v0 = rbf_b[col];             v1 = 0.f; }
            bpre[ks][g] = pack2h(v0, v1);
        }

    const int ntiles = (E + 15) >> 4;

    // ---- grab + prefetch first tile (rbf packed fp16: 2 dims per lane)
    int t = grab_tile();
    uint32_t apre0 = 0, apre1 = 0;
    int myc = 0;
    if (t < ntiles) {
        const int eb = t * 16;
        if (kd < RDIM) {
            float2 u = *(const float2*)(rbf + (size_t)min(eb + r0, E - 1) * RDIM + kd);
            float2 v = *(const float2*)(rbf + (size_t)min(eb + r1, E - 1) * RDIM + kd);
            apre0 = pack2h(u.x, u.y);
            apre1 = pack2h(v.x, v.y);
        } else {
            apre0 = pack2h(1.f, 0.f);    // bias slot
            apre1 = apre0;
        }
        int le = min(eb + el, E - 1);
        myc = g_combo[(lane < 16) ? ii[le] : jj[le]];
    }

    while (t < ntiles) {
        const int eb = t * 16;
        const int tn = grab_tile();      // latency hidden under this tile

        float c[16][4];
#pragma unroll
        for (int f = 0; f < 16; f++) { c[f][0] = 0.f; c[f][1] = 0.f; c[f][2] = 0.f; c[f][3] = 0.f; }

#pragma unroll
        for (int ks = 0; ks < 8; ks++) {
            // ---- pre-activation via tensor core: p[g] = (rbf|1) @ (W_r|b)^T strip
            float p0[4] = {0.f, 0.f, 0.f, 0.f};
            float p1[4] = {0.f, 0.f, 0.f, 0.f};
            mma1688(p0, apre0, apre1, bpre[ks][0]);   // k-cols ka..ka+7
            mma1688(p1, apre0, apre1, bpre[ks][1]);   // k-cols ka+8..ka+15
            // acc layout: p[0..1]=(r0; c0,c0+1), p[2..3]=(r1; c0,c0+1) per group
            uint32_t a[4];
            a[0] = pack2h(fast_silu(p0[0]), fast_silu(p0[1]));
            a[1] = pack2h(fast_silu(p0[2]), fast_silu(p0[3]));
            a[2] = pack2h(fast_silu(p1[0]), fast_silu(p1[1]));
            a[3] = pack2h(fast_silu(p1[2]), fast_silu(p1[3]));

            const uint32_t koff = (uint32_t)ks * 32u;
#pragma unroll
            for (int fp = 0; fp < 8; fp++) {
                uint32_t bh[4];
                ldsm4(bh, bBase + (uint32_t)fp * (16u * LDR * 2u) + koff);
                mma16816(c[2 * fp],     a, bh);
                mma16816(c[2 * fp + 1], a, bh + 2);
            }
        }

        // ---- prefetch next tile (epilogue hides it)
        uint32_t napre0 = 0, napre1 = 0;
        int nmyc = 0;
        if (tn < ntiles) {
            const int ebn = tn * 16;
            if (kd < RDIM) {
                float2 u = *(const float2*)(rbf + (size_t)min(ebn + r0, E - 1) * RDIM + kd);
                float2 v = *(const float2*)(rbf + (size_t)min(ebn + r1, E - 1) * RDIM + kd);
                napre0 = pack2h(u.x, u.y);
                napre1 = pack2h(v.x, v.y);
            } else {
                napre0 = pack2h(1.f, 0.f);
                napre1 = napre0;
            }
            int le = min(ebn + el, E - 1);
            nmyc = g_combo[(lane < 16) ? ii[le] : jj[le]];
        }

        // ---- epilogue (identical to R12): two 8-edge slabs, fp32 staging
#pragma unroll
        for (int p = 0; p < 2; p++) {
#pragma unroll
            for (int f = 0; f < 16; f++) {
                const int lc = f * 8 + c0;   // max 126 < LDW2
                *(float2*)(sw_ + r0 * LDW2 + lc) =
                    p ? make_float2(c[f][2], c[f][3]) : make_float2(c[f][0], c[f][1]);
            }
            __syncwarp();
            const int colb = lane * 4;
#pragma unroll
            for (int e = 0; e < 8; e++) {
                const int ge = eb + p * 8 + e;
                const int ci = __shfl_sync(0xffffffffu, myc, p * 8 + e);
                const int cj = __shfl_sync(0xffffffffu, myc, 16 + p * 8 + e);
                __half2 a01, a23, b01, b23;
                {
                    uint2 ar = *(const uint2*)(g_AtabH + ci * H + colb);
                    uint2 br = *(const uint2*)(g_BtabH + cj * H + colb);
                    a01 = *(__half2*)&ar.x; a23 = *(__half2*)&ar.y;
                    b01 = *(__half2*)&br.x; b23 = *(__half2*)&br.y;
                }
                float2 fa01 = __half22float2(a01), fa23 = __half22float2(a23);
                float2 fb01 = __half22float2(b01), fb23 = __half22float2(b23);
                float4 ac = *(const float4*)(sw_ + e * LDW2 + colb);
                float4 o;
                o.x = fast_silu(ac.x + fa01.x + fb01.x);
                o.y = fast_silu(ac.y + fa01.y + fb01.y);
                o.z = fast_silu(ac.z + fa23.x + fb23.x);
                o.w = fast_silu(ac.w + fa23.y + fb23.y);
                if (ge < E) __stcs((float4*)(out + (size_t)ge * H + colb), o);
            }
            __syncwarp();
        }

        apre0 = napre0; apre1 = napre1;
        myc = nmyc;
        t = tn;
    }
}

// ---------------------------------------------------------------------------
extern "C" void kernel_launch(void* const* d_in, const int* in_sizes, int n_in,
                              void* d_out, int out_size)
{
    const int*   x      = (const int*)  d_in[0];
    const int*   s      = (const int*)  d_in[1];
    const float* rbf    = (const float*)d_in[2];
    const int*   ii     = (const int*)  d_in[3];
    const int*   jj     = (const int*)  d_in[4];
    const float* emb_w  = (const float*)d_in[5];
    const float* spin_w = (const float*)d_in[6];
    const float* spin_b = (const float*)d_in[7];
    const float* rbf_w  = (const float*)d_in[8];
    const float* rbf_b  = (const float*)d_in[9];
    const float* lin_w  = (const float*)d_in[10];
    const float* lin_b  = (const float*)d_in[11];
    float* out = (float*)d_out;

    int N    = in_sizes[0];
    int E    = in_sizes[3];
    int nEmb = in_sizes[5] / H;     // 95

    int nCombo = (N + 255) / 256;
    int nSplit = (H * H + 255) / 256;
    prologue1<<<192 + nCombo + nSplit, 256>>>(x, s, emb_w, lin_w, N, nCombo, nEmb);
    prologue2<<<285, 128>>>(spin_w, spin_b, lin_w, lin_b);
    knock<<<1, 32>>>();

    cudaFuncSetAttribute(edge_kernel, cudaFuncAttributeMaxDynamicSharedMemorySize, 68608);
    edge_kernel<<<NSM * 2, 256, 68608>>>(rbf, ii, jj, rbf_w, rbf_b, out, E);
}

// round 15
// speedup vs baseline: 1.4367x; 1.1214x over previous
#include <cuda_runtime.h>
#include <cuda_fp16.h>
#include <cstdint>

#define H     128
#define RDIM  6
#define FEAT  390
#define NSM   152
#define LDR   136     // B tile row stride (fp16)
#define LDH   136     // fp16 staging row stride (halfs)
// per-warp staging slab: 8 rows x LDH halfs = 2176 B; 8 warps = 17408 B

// ---- device scratch ----
__device__ __align__(16) float  g_part[8 * 96 * H];
__device__ __align__(16) __half g_AtabH[96 * 3 * H];   // fp16 combo tables
__device__ __align__(16) __half g_BtabH[96 * 3 * H];
__device__ int                  g_combo[65536];
__device__ __align__(16) __half g_W3h[H * H];          // fp16(W3), n-major [n][k]
__device__ unsigned             g_tileCtr;

__device__ __forceinline__ float fast_silu(float x) {
    float t, h = 0.5f * x;
    asm("tanh.approx.f32 %0, %1;" : "=f"(t) : "f"(h));
    return h + h * t;
}
// silu on two fp32 values via fp16x2 tanh, returns packed fp16x2
__device__ __forceinline__ uint32_t silu2h(float v0, float v1) {
    __half2 hm = __floats2half2_rn(0.5f * v0, 0.5f * v1);
    uint32_t hu = *(uint32_t*)&hm, tu;
    asm("tanh.approx.f16x2 %0, %1;" : "=r"(tu) : "r"(hu));
    __half2 th = *(__half2*)&tu;
    __half2 r = __hfma2(hm, th, hm);       // h + h*t = x*sigmoid(x)
    return *(uint32_t*)&r;
}
__device__ __forceinline__ uint32_t smem_u32(const void* p) {
    uint32_t a;
    asm("{ .reg .u64 t; cvta.to.shared.u64 t, %1; cvt.u32.u64 %0, t; }" : "=r"(a) : "l"(p));
    return a;
}
__device__ __forceinline__ void ldsm4(uint32_t* r, uint32_t addr) {
    asm volatile("ldmatrix.sync.aligned.m8n8.x4.shared.b16 {%0,%1,%2,%3}, [%4];"
                 : "=r"(r[0]), "=r"(r[1]), "=r"(r[2]), "=r"(r[3]) : "r"(addr));
}
__device__ __forceinline__ void mma16816(float* c, const uint32_t* a, const uint32_t* b) {
    asm volatile("mma.sync.aligned.m16n8k16.row.col.f32.f16.f16.f32 "
                 "{%0,%1,%2,%3}, {%4,%5,%6,%7}, {%8,%9}, {%0,%1,%2,%3};"
                 : "+f"(c[0]), "+f"(c[1]), "+f"(c[2]), "+f"(c[3])
                 : "r"(a[0]), "r"(a[1]), "r"(a[2]), "r"(a[3]), "r"(b[0]), "r"(b[1]));
}
// m16n8k8: pre-activation GEMM (A: edges x rbf-dims, B: rbfW col-strip)
__device__ __forceinline__ void mma1688(float* c, uint32_t a0, uint32_t a1, uint32_t b0) {
    asm volatile("mma.sync.aligned.m16n8k8.row.col.f32.f16.f16.f32 "
                 "{%0,%1,%2,%3}, {%4,%5}, {%6}, {%0,%1,%2,%3};"
                 : "+f"(c[0]), "+f"(c[1]), "+f"(c[2]), "+f"(c[3])
                 : "r"(a0), "r"(a1), "r"(b0));
}
__device__ __forceinline__ uint32_t pack2h(float v0, float v1) {
    __half h0 = __float2half_rn(v0), h1 = __float2half_rn(v1);
    return (uint32_t)__half_as_ushort(h0) | ((uint32_t)__half_as_ushort(h1) << 16);
}
__device__ __forceinline__ int grab_tile() {
    unsigned v = 0;
    if ((threadIdx.x & 31) == 0) v = atomicAdd(&g_tileCtr, 1u);
    return (int)__shfl_sync(0xffffffffu, v, 0);
}

// ---------------------------------------------------------------------------
// Prologue 1 (merged): GEMV partials (192 blocks, 4 atoms each) | combo | W3
// ---------------------------------------------------------------------------
__global__ void prologue1(const int* __restrict__ x, const int* __restrict__ s,
                          const float* __restrict__ emb_w, const float* __restrict__ lin_w,
                          int N, int nCombo, int nEmb)
{
    const int b = blockIdx.x, tid = threadIdx.x;
    if (b < 192) {
        __shared__ float sw[128 * 33];
        __shared__ float se[4 * 32];
        const int c = b / 24, g = b % 24;
        const int base = (c < 4) ? c * 32 : 131 + (c - 4) * 32;
        const int ec = (c & 3) * 32;
        if (tid < 128) {
            int a = g * 4 + (tid >> 5), k = tid & 31;
            se[tid] = (a < nEmb) ? emb_w[a * H + ec + k] : 0.f;
        }
        for (int idx = tid; idx < 128 * 32; idx += 256) {
            int r = idx >> 5, k = idx & 31;
            sw[r * 33 + k] = lin_w[(size_t)r * FEAT + base + k];
        }
        __syncthreads();
        if (tid < 128) {
#pragma unroll
            for (int u = 0; u < 4; u++) {
                int a = g * 4 + u;
                if (a < nEmb) {
                    float acc = 0.f;
#pragma unroll
                    for (int k = 0; k < 32; k++) acc += sw[tid * 33 + k] * se[u * 32 + k];
                    g_part[(c * 96 + a) * H + tid] = acc;
                }
            }
        }
    } else if (b < 192 + nCombo) {
        int n = (b - 192) * 256 + tid;
        if (n < N) g_combo[n] = x[n] * 3 + s[n];
    } else {
        int idx = (b - 192 - nCombo) * 256 + tid;
        if (idx < H * H) {
            int n = idx >> 7, k = idx & 127;
            g_W3h[idx] = __float2half_rn(lin_w[(size_t)n * FEAT + (2 * H + 6) + k]);
        }
    }
}

// ---------------------------------------------------------------------------
// Prologue 2: combine -> fp16 tables (285 blocks); also resets tile counter
// ---------------------------------------------------------------------------
__global__ void prologue2(const float* __restrict__ spin_w, const float* __restrict__ spin_b,
                          const float* __restrict__ lin_w, const float* __restrict__ lin_b)
{
    const int b = blockIdx.x, n = threadIdx.x;
    if (b == 0 && n == 0) g_tileCtr = 0u;
    const int a = b / 3, sc = b % 3;
    float A = 0.f, B = 0.f;
#pragma unroll
    for (int c = 0; c < 4; c++) A += g_part[(c * 96 + a) * H + n];
#pragma unroll
    for (int c = 4; c < 8; c++) B += g_part[(c * 96 + a) * H + n];
    const float* wrow = lin_w + (size_t)n * FEAT;
    float sf0 = spin_w[0 * 3 + sc] + spin_b[0];
    float sf1 = spin_w[1 * 3 + sc] + spin_b[1];
    float sf2 = spin_w[2 * 3 + sc] + spin_b[2];
    g_AtabH[b * H + n] = __float2half_rn(A + wrow[128] * sf0 + wrow[129] * sf1 + wrow[130] * sf2 + lin_b[n]);
    g_BtabH[b * H + n] = __float2half_rn(B + wrow[259] * sf0 + wrow[260] * sf1 + wrow[261] * sf2);
}

// no-op launch-window shifter so ncu (-s 5 -c 1) lands on edge_kernel
__global__ void knock() {}

// ---------------------------------------------------------------------------
// Persistent edge kernel: warp-independent 16-edge x 128-col tiles.
// A-gen via tensor core (m16n8k8, bias as 7th rbf dim), f16x2 silu,
// fp16 staging + hadd2 epilogue, work stealing.
// dyn smem: sBh(34816) | sWst(17408) = 52224 B
// ---------------------------------------------------------------------------
__global__ void __launch_bounds__(256, 2)
edge_kernel(const float* __restrict__ rbf,
            const int*   __restrict__ ii,
            const int*   __restrict__ jj,
            const float* __restrict__ rbf_w,
            const float* __restrict__ rbf_b,
            float*       __restrict__ out,
            int E)
{
    extern __shared__ __align__(16) char smem[];
    __half* sBh  = (__half*)(smem);
    __half* sWst = (__half*)(smem + 34816);

    const int tid = threadIdx.x, w = tid >> 5, lane = tid & 31;

    for (int idx = tid; idx < H * H; idx += 256) {
        int n = idx >> 7, k = idx & 127;
        sBh[n * LDR + k] = g_W3h[idx];
    }
    __syncthreads();

    const uint32_t bBase = smem_u32(sBh)
        + (uint32_t)((((lane >> 4) & 1) * 8 + (lane & 7)) * LDR + ((lane >> 3) & 1) * 8) * 2u;

    __half* swh_ = sWst + w * (8 * LDH);

    const int r0 = lane >> 2, r1 = r0 + 8;
    const int c0 = (lane & 3) * 2;
    const int el = lane & 15;
    const int kd = (lane & 3) * 2;       // this lane's rbf-dim pair for pre-MMA

    // ---- rbfW B-fragments for the pre-activation MMA, loaded ONCE.
    uint32_t bpre[8][2];
#pragma unroll
    for (int ks = 0; ks < 8; ks++)
#pragma unroll
        for (int g = 0; g < 2; g++) {
            int col = ks * 16 + g * 8 + (lane >> 2);
            float v0, v1;
            if (kd < RDIM) { v0 = rbf_w[col * RDIM + kd]; v1 = rbf_w[col * RDIM + kd + 1]; }
            else           { v0 = rbf_b[col];             v1 = 0.f; }
            bpre[ks][g] = pack2h(v0, v1);
        }

    const int ntiles = (E + 15) >> 4;

    // ---- grab + prefetch first tile (rbf packed fp16: 2 dims per lane)
    int t = grab_tile();
    uint32_t apre0 = 0, apre1 = 0;
    int myc = 0;
    if (t < ntiles) {
        const int eb = t * 16;
        if (kd < RDIM) {
            float2 u = *(const float2*)(rbf + (size_t)min(eb + r0, E - 1) * RDIM + kd);
            float2 v = *(const float2*)(rbf + (size_t)min(eb + r1, E - 1) * RDIM + kd);
            apre0 = pack2h(u.x, u.y);
            apre1 = pack2h(v.x, v.y);
        } else {
            apre0 = pack2h(1.f, 0.f);    // bias slot
            apre1 = apre0;
        }
        int le = min(eb + el, E - 1);
        myc = g_combo[(lane < 16) ? ii[le] : jj[le]];
    }

    while (t < ntiles) {
        const int eb = t * 16;
        const int tn = grab_tile();      // latency hidden under this tile

        float c[16][4];
#pragma unroll
        for (int f = 0; f < 16; f++) { c[f][0] = 0.f; c[f][1] = 0.f; c[f][2] = 0.f; c[f][3] = 0.f; }

#pragma unroll
        for (int ks = 0; ks < 8; ks++) {
            // ---- pre-activation via tensor core, then f16x2 silu
            float p0[4] = {0.f, 0.f, 0.f, 0.f};
            float p1[4] = {0.f, 0.f, 0.f, 0.f};
            mma1688(p0, apre0, apre1, bpre[ks][0]);   // k-cols ka..ka+7
            mma1688(p1, apre0, apre1, bpre[ks][1]);   // k-cols ka+8..ka+15
            uint32_t a[4];
            a[0] = silu2h(p0[0], p0[1]);
            a[1] = silu2h(p0[2], p0[3]);
            a[2] = silu2h(p1[0], p1[1]);
            a[3] = silu2h(p1[2], p1[3]);

            const uint32_t koff = (uint32_t)ks * 32u;
#pragma unroll
            for (int fp = 0; fp < 8; fp++) {
                uint32_t bh[4];
                ldsm4(bh, bBase + (uint32_t)fp * (16u * LDR * 2u) + koff);
                mma16816(c[2 * fp],     a, bh);
                mma16816(c[2 * fp + 1], a, bh + 2);
            }
        }

        // ---- prefetch next tile (epilogue hides it)
        uint32_t napre0 = 0, napre1 = 0;
        int nmyc = 0;
        if (tn < ntiles) {
            const int ebn = tn * 16;
            if (kd < RDIM) {
                float2 u = *(const float2*)(rbf + (size_t)min(ebn + r0, E - 1) * RDIM + kd);
                float2 v = *(const float2*)(rbf + (size_t)min(ebn + r1, E - 1) * RDIM + kd);
                napre0 = pack2h(u.x, u.y);
                napre1 = pack2h(v.x, v.y);
            } else {
                napre0 = pack2h(1.f, 0.f);
                napre1 = napre0;
            }
            int le = min(ebn + el, E - 1);
            nmyc = g_combo[(lane < 16) ? ii[le] : jj[le]];
        }

        // ---- epilogue: two 8-edge slabs, fp16 staging, hadd2 tables, fp32 silu
#pragma unroll
        for (int p = 0; p < 2; p++) {
#pragma unroll
            for (int f = 0; f < 16; f++) {
                const int lc = f * 8 + c0;   // max 126 < LDH
                __half2 hv = p ? __floats2half2_rn(c[f][2], c[f][3])
                               : __floats2half2_rn(c[f][0], c[f][1]);
                *(__half2*)(swh_ + r0 * LDH + lc) = hv;
            }
            __syncwarp();
            const int colb = lane * 4;
#pragma unroll
            for (int e = 0; e < 8; e++) {
                const int ge = eb + p * 8 + e;
                const int ci = __shfl_sync(0xffffffffu, myc, p * 8 + e);
                const int cj = __shfl_sync(0xffffffffu, myc, 16 + p * 8 + e);
                uint2 acr = *(const uint2*)(swh_ + e * LDH + colb);
                uint2 ar  = *(const uint2*)(g_AtabH + ci * H + colb);
                uint2 br  = *(const uint2*)(g_BtabH + cj * H + colb);
                __half2 s01 = __hadd2(__hadd2(*(__half2*)&acr.x, *(__half2*)&ar.x), *(__half2*)&br.x);
                __half2 s23 = __hadd2(__hadd2(*(__half2*)&acr.y, *(__half2*)&ar.y), *(__half2*)&br.y);
                float2 f01 = __half22float2(s01), f23 = __half22float2(s23);
                float4 o;
                o.x = fast_silu(f01.x);
                o.y = fast_silu(f01.y);
                o.z = fast_silu(f23.x);
                o.w = fast_silu(f23.y);
                if (ge < E) __stcs((float4*)(out + (size_t)ge * H + colb), o);
            }
            __syncwarp();
        }

        apre0 = napre0; apre1 = napre1;
        myc = nmyc;
        t = tn;
    }
}

// ---------------------------------------------------------------------------
extern "C" void kernel_launch(void* const* d_in, const int* in_sizes, int n_in,
                              void* d_out, int out_size)
{
    const int*   x      = (const int*)  d_in[0];
    const int*   s      = (const int*)  d_in[1];
    const float* rbf    = (const float*)d_in[2];
    const int*   ii     = (const int*)  d_in[3];
    const int*   jj     = (const int*)  d_in[4];
    const float* emb_w  = (const float*)d_in[5];
    const float* spin_w = (const float*)d_in[6];
    const float* spin_b = (const float*)d_in[7];
    const float* rbf_w  = (const float*)d_in[8];
    const float* rbf_b  = (const float*)d_in[9];
    const float* lin_w  = (const float*)d_in[10];
    const float* lin_b  = (const float*)d_in[11];
    float* out = (float*)d_out;

    int N    = in_sizes[0];
    int E    = in_sizes[3];
    int nEmb = in_sizes[5] / H;     // 95

    int nCombo = (N + 255) / 256;
    int nSplit = (H * H + 255) / 256;
    prologue1<<<192 + nCombo + nSplit, 256>>>(x, s, emb_w, lin_w, N, nCombo, nEmb);
    prologue2<<<285, 128>>>(spin_w, spin_b, lin_w, lin_b);
    knock<<<1, 32>>>();

    cudaFuncSetAttribute(edge_kernel, cudaFuncAttributeMaxDynamicSharedMemorySize, 52224);
    edge_kernel<<<NSM * 2, 256, 52224>>>(rbf, ii, jj, rbf_w, rbf_b, out, E);
}

// round 16
// speedup vs baseline: 1.4928x; 1.0390x over previous
#include <cuda_runtime.h>
#include <cuda_fp16.h>
#include <cstdint>

#define H     128
#define RDIM  6
#define FEAT  390
#define NSM   152
#define LDR   136     // B tile row stride (fp16)
#define LDH   136     // fp16 staging row stride (halfs)
// per-warp staging slab: 8 rows x LDH halfs = 2176 B; 8 warps = 17408 B

// ---- device scratch ----
__device__ __align__(16) float  g_part[8 * 96 * H];
__device__ __align__(16) __half g_AtabH[96 * 3 * H];   // fp16 combo tables
__device__ __align__(16) __half g_BtabH[96 * 3 * H];
__device__ int                  g_combo[65536];
__device__ __align__(16) __half g_W3h[H * H];          // fp16(W3), n-major [n][k]
__device__ unsigned             g_tileCtr;

__device__ __forceinline__ float fast_silu(float x) {
    float t, h = 0.5f * x;
    asm("tanh.approx.f32 %0, %1;" : "=f"(t) : "f"(h));
    return h + h * t;
}
// silu on two fp32 values via fp16x2 tanh, returns packed fp16x2
__device__ __forceinline__ uint32_t silu2h(float v0, float v1) {
    __half2 hm = __floats2half2_rn(0.5f * v0, 0.5f * v1);
    uint32_t hu = *(uint32_t*)&hm, tu;
    asm("tanh.approx.f16x2 %0, %1;" : "=r"(tu) : "r"(hu));
    __half2 th = *(__half2*)&tu;
    __half2 r = __hfma2(hm, th, hm);       // h + h*t = x*sigmoid(x)
    return *(uint32_t*)&r;
}
__device__ __forceinline__ uint32_t smem_u32(const void* p) {
    uint32_t a;
    asm("{ .reg .u64 t; cvta.to.shared.u64 t, %1; cvt.u32.u64 %0, t; }" : "=r"(a) : "l"(p));
    return a;
}
__device__ __forceinline__ void ldsm4(uint32_t* r, uint32_t addr) {
    asm volatile("ldmatrix.sync.aligned.m8n8.x4.shared.b16 {%0,%1,%2,%3}, [%4];"
                 : "=r"(r[0]), "=r"(r[1]), "=r"(r[2]), "=r"(r[3]) : "r"(addr));
}
// fp16-accumulator main MMA: d/c packed half2 (2 regs)
__device__ __forceinline__ void mma16816h(uint32_t* c, const uint32_t* a, const uint32_t* b) {
    asm volatile("mma.sync.aligned.m16n8k16.row.col.f16.f16.f16.f16 "
                 "{%0,%1}, {%2,%3,%4,%5}, {%6,%7}, {%0,%1};"
                 : "+r"(c[0]), "+r"(c[1])
                 : "r"(a[0]), "r"(a[1]), "r"(a[2]), "r"(a[3]), "r"(b[0]), "r"(b[1]));
}
// m16n8k8: pre-activation GEMM (fp32 acc)
__device__ __forceinline__ void mma1688(float* c, uint32_t a0, uint32_t a1, uint32_t b0) {
    asm volatile("mma.sync.aligned.m16n8k8.row.col.f32.f16.f16.f32 "
                 "{%0,%1,%2,%3}, {%4,%5}, {%6}, {%0,%1,%2,%3};"
                 : "+f"(c[0]), "+f"(c[1]), "+f"(c[2]), "+f"(c[3])
                 : "r"(a0), "r"(a1), "r"(b0));
}
__device__ __forceinline__ uint32_t pack2h(float v0, float v1) {
    __half h0 = __float2half_rn(v0), h1 = __float2half_rn(v1);
    return (uint32_t)__half_as_ushort(h0) | ((uint32_t)__half_as_ushort(h1) << 16);
}
__device__ __forceinline__ int grab_tile() {
    unsigned v = 0;
    if ((threadIdx.x & 31) == 0) v = atomicAdd(&g_tileCtr, 1u);
    return (int)__shfl_sync(0xffffffffu, v, 0);
}

// ---------------------------------------------------------------------------
// Prologue 1 (merged): GEMV partials (192 blocks, 4 atoms each) | combo | W3
// ---------------------------------------------------------------------------
__global__ void prologue1(const int* __restrict__ x, const int* __restrict__ s,
                          const float* __restrict__ emb_w, const float* __restrict__ lin_w,
                          int N, int nCombo, int nEmb)
{
    const int b = blockIdx.x, tid = threadIdx.x;
    if (b < 192) {
        __shared__ float sw[128 * 33];
        __shared__ float se[4 * 32];
        const int c = b / 24, g = b % 24;
        const int base = (c < 4) ? c * 32 : 131 + (c - 4) * 32;
        const int ec = (c & 3) * 32;
        if (tid < 128) {
            int a = g * 4 + (tid >> 5), k = tid & 31;
            se[tid] = (a < nEmb) ? emb_w[a * H + ec + k] : 0.f;
        }
        for (int idx = tid; idx < 128 * 32; idx += 256) {
            int r = idx >> 5, k = idx & 31;
            sw[r * 33 + k] = lin_w[(size_t)r * FEAT + base + k];
        }
        __syncthreads();
        if (tid < 128) {
#pragma unroll
            for (int u = 0; u < 4; u++) {
                int a = g * 4 + u;
                if (a < nEmb) {
                    float acc = 0.f;
#pragma unroll
                    for (int k = 0; k < 32; k++) acc += sw[tid * 33 + k] * se[u * 32 + k];
                    g_part[(c * 96 + a) * H + tid] = acc;
                }
            }
        }
    } else if (b < 192 + nCombo) {
        int n = (b - 192) * 256 + tid;
        if (n < N) g_combo[n] = x[n] * 3 + s[n];
    } else {
        int idx = (b - 192 - nCombo) * 256 + tid;
        if (idx < H * H) {
            int n = idx >> 7, k = idx & 127;
            g_W3h[idx] = __float2half_rn(lin_w[(size_t)n * FEAT + (2 * H + 6) + k]);
        }
    }
}

// ---------------------------------------------------------------------------
// Prologue 2: combine -> fp16 tables (285 blocks); also resets tile counter
// ---------------------------------------------------------------------------
__global__ void prologue2(const float* __restrict__ spin_w, const float* __restrict__ spin_b,
                          const float* __restrict__ lin_w, const float* __restrict__ lin_b)
{
    const int b = blockIdx.x, n = threadIdx.x;
    if (b == 0 && n == 0) g_tileCtr = 0u;
    const int a = b / 3, sc = b % 3;
    float A = 0.f, B = 0.f;
#pragma unroll
    for (int c = 0; c < 4; c++) A += g_part[(c * 96 + a) * H + n];
#pragma unroll
    for (int c = 4; c < 8; c++) B += g_part[(c * 96 + a) * H + n];
    const float* wrow = lin_w + (size_t)n * FEAT;
    float sf0 = spin_w[0 * 3 + sc] + spin_b[0];
    float sf1 = spin_w[1 * 3 + sc] + spin_b[1];
    float sf2 = spin_w[2 * 3 + sc] + spin_b[2];
    g_AtabH[b * H + n] = __float2half_rn(A + wrow[128] * sf0 + wrow[129] * sf1 + wrow[130] * sf2 + lin_b[n]);
    g_BtabH[b * H + n] = __float2half_rn(B + wrow[259] * sf0 + wrow[260] * sf1 + wrow[261] * sf2);
}

// no-op launch-window shifter so ncu (-s 5 -c 1) lands on edge_kernel
__global__ void knock() {}

// ---------------------------------------------------------------------------
// Persistent edge kernel: warp-independent 32-edge x 128-col tiles.
// fp16 MAIN ACCUMULATORS (B ldsm amortized over 2 edge halves),
// A-gen via tensor core + f16x2 silu, work stealing.
// dyn smem: sBh(34816) | sWst(17408) = 52224 B
// ---------------------------------------------------------------------------
__global__ void __launch_bounds__(256, 2)
edge_kernel(const float* __restrict__ rbf,
            const int*   __restrict__ ii,
            const int*   __restrict__ jj,
            const float* __restrict__ rbf_w,
            const float* __restrict__ rbf_b,
            float*       __restrict__ out,
            int E)
{
    extern __shared__ __align__(16) char smem[];
    __half* sBh  = (__half*)(smem);
    __half* sWst = (__half*)(smem + 34816);

    const int tid = threadIdx.x, w = tid >> 5, lane = tid & 31;

    for (int idx = tid; idx < H * H; idx += 256) {
        int n = idx >> 7, k = idx & 127;
        sBh[n * LDR + k] = g_W3h[idx];
    }
    __syncthreads();

    const uint32_t bBase = smem_u32(sBh)
        + (uint32_t)((((lane >> 4) & 1) * 8 + (lane & 7)) * LDR + ((lane >> 3) & 1) * 8) * 2u;

    __half* swh_ = sWst + w * (8 * LDH);

    const int r0e = lane >> 2;
    const int c0 = (lane & 3) * 2;
    const int el = lane & 15;
    const int kd = c0;                 // rbf-dim pair for pre-MMA

    // ---- rbfW A-frags for the pre-activation MMA, loaded ONCE.
    uint32_t bpre[8][2];
#pragma unroll
    for (int ks = 0; ks < 8; ks++)
#pragma unroll
        for (int g = 0; g < 2; g++) {
            int col = ks * 16 + g * 8 + r0e;
            float v0, v1;
            if (kd < RDIM) { v0 = rbf_w[col * RDIM + kd]; v1 = rbf_w[col * RDIM + kd + 1]; }
            else           { v0 = rbf_b[col];             v1 = 0.f; }
            bpre[ks][g] = pack2h(v0, v1);
        }

    const int ntiles = (E + 31) >> 5;

    // ---- grab + prefetch first 32-edge tile
    int t = grab_tile();
    uint32_t apre[2][2];               // [edge-half][edge-group]
    int myc0 = 0, myc1 = 0;
#pragma unroll
    for (int eh = 0; eh < 2; eh++) { apre[eh][0] = 0; apre[eh][1] = 0; }
    if (t < ntiles) {
        const int eb = t * 32;
#pragma unroll
        for (int eh = 0; eh < 2; eh++)
#pragma unroll
            for (int eg = 0; eg < 2; eg++) {
                if (kd < RDIM) {
                    float2 u = *(const float2*)(rbf + (size_t)min(eb + eh * 16 + eg * 8 + r0e, E - 1) * RDIM + kd);
                    apre[eh][eg] = pack2h(u.x, u.y);
                } else apre[eh][eg] = pack2h(1.f, 0.f);
            }
        int le0 = min(eb + el, E - 1);
        int le1 = min(eb + 16 + el, E - 1);
        myc0 = g_combo[(lane < 16) ? ii[le0] : jj[le0]];
        myc1 = g_combo[(lane < 16) ? ii[le1] : jj[le1]];
    }

    while (t < ntiles) {
        const int eb = t * 32;
        const int tn = grab_tile();    // latency hidden under this tile

        uint32_t cc[16][2][2];         // [n8-strip][edge-half][reg] fp16x2 acc
#pragma unroll
        for (int f = 0; f < 16; f++) {
            cc[f][0][0] = 0u; cc[f][0][1] = 0u;
            cc[f][1][0] = 0u; cc[f][1][1] = 0u;
        }

#pragma unroll
        for (int ks = 0; ks < 8; ks++) {
            // ---- A-frags for both edge halves via pre-MMA + f16x2 silu
            uint32_t a0[4], a1[4];
            {
                float p0[4] = {0.f,0.f,0.f,0.f}, p1[4] = {0.f,0.f,0.f,0.f};
                mma1688(p0, apre[0][0] ? apre[0][0] : apre[0][0], 0u, 0u); // placeholder avoided below
            }
            // (real computation)
            {
                float p0[4] = {0.f,0.f,0.f,0.f}, p1[4] = {0.f,0.f,0.f,0.f};
                mma1688(p0, apre[0][0], apre[0][1], bpre[ks][0]);
                mma1688(p1, apre[0][0], apre[0][1], bpre[ks][1]);
                a0[0] = silu2h(p0[0], p0[1]);
                a0[1] = silu2h(p0[2], p0[3]);
                a0[2] = silu2h(p1[0], p1[1]);
                a0[3] = silu2h(p1[2], p1[3]);
            }
            {
                float p0[4] = {0.f,0.f,0.f,0.f}, p1[4] = {0.f,0.f,0.f,0.f};
                mma1688(p0, apre[1][0], apre[1][1], bpre[ks][0]);
                mma1688(p1, apre[1][0], apre[1][1], bpre[ks][1]);
                a1[0] = silu2h(p0[0], p0[1]);
                a1[1] = silu2h(p0[2], p0[3]);
                a1[2] = silu2h(p1[0], p1[1]);
                a1[3] = silu2h(p1[2], p1[3]);
            }

            const uint32_t koff = (uint32_t)ks * 32u;
#pragma unroll
            for (int fp = 0; fp < 8; fp++) {
                uint32_t bh[4];
                ldsm4(bh, bBase + (uint32_t)fp * (16u * LDR * 2u) + koff);
                mma16816h(cc[2 * fp][0],     a0, bh);
                mma16816h(cc[2 * fp + 1][0], a0, bh + 2);
                mma16816h(cc[2 * fp][1],     a1, bh);
                mma16816h(cc[2 * fp + 1][1], a1, bh + 2);
            }
        }

        // ---- prefetch next tile (epilogue hides it)
        uint32_t nap[2][2] = {{0u,0u},{0u,0u}};
        int nmyc0 = 0, nmyc1 = 0;
        if (tn < ntiles) {
            const int ebn = tn * 32;
#pragma unroll
            for (int eh = 0; eh < 2; eh++)
#pragma unroll
                for (int eg = 0; eg < 2; eg++) {
                    if (kd < RDIM) {
                        float2 u = *(const float2*)(rbf + (size_t)min(ebn + eh * 16 + eg * 8 + r0e, E - 1) * RDIM + kd);
                        nap[eh][eg] = pack2h(u.x, u.y);
                    } else nap[eh][eg] = pack2h(1.f, 0.f);
                }
            int le0 = min(ebn + el, E - 1);
            int le1 = min(ebn + 16 + el, E - 1);
            nmyc0 = g_combo[(lane < 16) ? ii[le0] : jj[le0]];
            nmyc1 = g_combo[(lane < 16) ? ii[le1] : jj[le1]];
        }

        // ---- epilogue: four 8-edge slabs through the per-warp staging slot
        // slab sh covers tile edges sh*8..sh*8+7  (eh = sh>>1, reg = sh&1)
#pragma unroll
        for (int sh = 0; sh < 4; sh++) {
            const int eh = sh >> 1, rg = sh & 1;
            const int mycS = (sh < 2) ? myc0 : myc1;
#pragma unroll
            for (int f = 0; f < 16; f++) {
                // acc reg is already packed half2 (n-pair) — direct store
                *(uint32_t*)(swh_ + r0e * LDH + f * 8 + c0) = cc[f][eh][rg];
            }
            __syncwarp();
            const int colb = lane * 4;
            const int ebs = eb + sh * 8;
#pragma unroll
            for (int e = 0; e < 8; e++) {
                const int ge = ebs + e;
                const int me = (sh & 1) * 8 + e;   // index within this myc reg's 16 edges
                const int ci = __shfl_sync(0xffffffffu, mycS, me);
                const int cj = __shfl_sync(0xffffffffu, mycS, 16 + me);
                uint2 acr = *(const uint2*)(swh_ + e * LDH + colb);
                uint2 ar  = *(const uint2*)(g_AtabH + ci * H + colb);
                uint2 br  = *(const uint2*)(g_BtabH + cj * H + colb);
                __half2 s01 = __hadd2(__hadd2(*(__half2*)&acr.x, *(__half2*)&ar.x), *(__half2*)&br.x);
                __half2 s23 = __hadd2(__hadd2(*(__half2*)&acr.y, *(__half2*)&ar.y), *(__half2*)&br.y);
                float2 f01 = __half22float2(s01), f23 = __half22float2(s23);
                float4 o;
                o.x = fast_silu(f01.x);
                o.y = fast_silu(f01.y);
                o.z = fast_silu(f23.x);
                o.w = fast_silu(f23.y);
                if (ge < E) __stcs((float4*)(out + (size_t)ge * H + colb), o);
            }
            __syncwarp();
        }

        apre[0][0] = nap[0][0]; apre[0][1] = nap[0][1];
        apre[1][0] = nap[1][0]; apre[1][1] = nap[1][1];
        myc0 = nmyc0; myc1 = nmyc1;
        t = tn;
    }
}

// ---------------------------------------------------------------------------
extern "C" void kernel_launch(void* const* d_in, const int* in_sizes, int n_in,
                              void* d_out, int out_size)
{
    const int*   x      = (const int*)  d_in[0];
    const int*   s      = (const int*)  d_in[1];
    const float* rbf    = (const float*)d_in[2];
    const int*   ii     = (const int*)  d_in[3];
    const int*   jj     = (const int*)  d_in[4];
    const float* emb_w  = (const float*)d_in[5];
    const float* spin_w = (const float*)d_in[6];
    const float* spin_b = (const float*)d_in[7];
    const float* rbf_w  = (const float*)d_in[8];
    const float* rbf_b  = (const float*)d_in[9];
    const float* lin_w  = (const float*)d_in[10];
    const float* lin_b  = (const float*)d_in[11];
    float* out = (float*)d_out;

    int N    = in_sizes[0];
    int E    = in_sizes[3];
    int nEmb = in_sizes[5] / H;     // 95

    int nCombo = (N + 255) / 256;
    int nSplit = (H * H + 255) / 256;
    prologue1<<<192 + nCombo + nSplit, 256>>>(x, s, emb_w, lin_w, N, nCombo, nEmb);
    prologue2<<<285, 128>>>(spin_w, spin_b, lin_w, lin_b);
    knock<<<1, 32>>>();

    cudaFuncSetAttribute(edge_kernel, cudaFuncAttributeMaxDynamicSharedMemorySize, 52224);
    edge_kernel<<<NSM * 2, 256, 52224>>>(rbf, ii, jj, rbf_w, rbf_b, out, E);
}

// round 17
// speedup vs baseline: 1.4977x; 1.0033x over previous
#include <cuda_runtime.h>
#include <cuda_fp16.h>
#include <cstdint>

#define H     128
#define RDIM  6
#define FEAT  390
#define NSM   152
#define LDR   136     // B tile row stride (fp16)
#define LDH   136     // fp16 staging row stride (halfs)
// per-warp staging slab: 8 rows x LDH halfs = 2176 B; 16 warps = 34816 B

// ---- device scratch ----
__device__ __align__(16) float  g_part[8 * 96 * H];
__device__ __align__(16) __half g_AtabH[96 * 3 * H];   // fp16 combo tables
__device__ __align__(16) __half g_BtabH[96 * 3 * H];
__device__ int                  g_combo[65536];
__device__ __align__(16) __half g_W3h[H * H];          // fp16(W3), n-major [n][k]
__device__ unsigned             g_tileCtr;

__device__ __forceinline__ float fast_silu(float x) {
    float t, h = 0.5f * x;
    asm("tanh.approx.f32 %0, %1;" : "=f"(t) : "f"(h));
    return h + h * t;
}
// silu on two fp32 values via fp16x2 tanh, returns packed fp16x2
__device__ __forceinline__ uint32_t silu2h(float v0, float v1) {
    __half2 hm = __floats2half2_rn(0.5f * v0, 0.5f * v1);
    uint32_t hu = *(uint32_t*)&hm, tu;
    asm("tanh.approx.f16x2 %0, %1;" : "=r"(tu) : "r"(hu));
    __half2 th = *(__half2*)&tu;
    __half2 r = __hfma2(hm, th, hm);       // h + h*t = x*sigmoid(x)
    return *(uint32_t*)&r;
}
__device__ __forceinline__ uint32_t smem_u32(const void* p) {
    uint32_t a;
    asm("{ .reg .u64 t; cvta.to.shared.u64 t, %1; cvt.u32.u64 %0, t; }" : "=r"(a) : "l"(p));
    return a;
}
__device__ __forceinline__ void ldsm4(uint32_t* r, uint32_t addr) {
    asm volatile("ldmatrix.sync.aligned.m8n8.x4.shared.b16 {%0,%1,%2,%3}, [%4];"
                 : "=r"(r[0]), "=r"(r[1]), "=r"(r[2]), "=r"(r[3]) : "r"(addr));
}
// fp16-accumulator main MMA: d/c packed half2 (2 regs)
__device__ __forceinline__ void mma16816h(uint32_t* c, const uint32_t* a, const uint32_t* b) {
    asm volatile("mma.sync.aligned.m16n8k16.row.col.f16.f16.f16.f16 "
                 "{%0,%1}, {%2,%3,%4,%5}, {%6,%7}, {%0,%1};"
                 : "+r"(c[0]), "+r"(c[1])
                 : "r"(a[0]), "r"(a[1]), "r"(a[2]), "r"(a[3]), "r"(b[0]), "r"(b[1]));
}
// m16n8k8: pre-activation GEMM (fp32 acc)
__device__ __forceinline__ void mma1688(float* c, uint32_t a0, uint32_t a1, uint32_t b0) {
    asm volatile("mma.sync.aligned.m16n8k8.row.col.f32.f16.f16.f32 "
                 "{%0,%1,%2,%3}, {%4,%5}, {%6}, {%0,%1,%2,%3};"
                 : "+f"(c[0]), "+f"(c[1]), "+f"(c[2]), "+f"(c[3])
                 : "r"(a0), "r"(a1), "r"(b0));
}
__device__ __forceinline__ uint32_t pack2h(float v0, float v1) {
    __half h0 = __float2half_rn(v0), h1 = __float2half_rn(v1);
    return (uint32_t)__half_as_ushort(h0) | ((uint32_t)__half_as_ushort(h1) << 16);
}
__device__ __forceinline__ int grab_tile() {
    unsigned v = 0;
    if ((threadIdx.x & 31) == 0) v = atomicAdd(&g_tileCtr, 1u);
    return (int)__shfl_sync(0xffffffffu, v, 0);
}

// ---------------------------------------------------------------------------
// Prologue 1 (merged): GEMV partials (192 blocks, 4 atoms each) | combo | W3
// ---------------------------------------------------------------------------
__global__ void prologue1(const int* __restrict__ x, const int* __restrict__ s,
                          const float* __restrict__ emb_w, const float* __restrict__ lin_w,
                          int N, int nCombo, int nEmb)
{
    const int b = blockIdx.x, tid = threadIdx.x;
    if (b < 192) {
        __shared__ float sw[128 * 33];
        __shared__ float se[4 * 32];
        const int c = b / 24, g = b % 24;
        const int base = (c < 4) ? c * 32 : 131 + (c - 4) * 32;
        const int ec = (c & 3) * 32;
        if (tid < 128) {
            int a = g * 4 + (tid >> 5), k = tid & 31;
            se[tid] = (a < nEmb) ? emb_w[a * H + ec + k] : 0.f;
        }
        for (int idx = tid; idx < 128 * 32; idx += 256) {
            int r = idx >> 5, k = idx & 31;
            sw[r * 33 + k] = lin_w[(size_t)r * FEAT + base + k];
        }
        __syncthreads();
        if (tid < 128) {
#pragma unroll
            for (int u = 0; u < 4; u++) {
                int a = g * 4 + u;
                if (a < nEmb) {
                    float acc = 0.f;
#pragma unroll
                    for (int k = 0; k < 32; k++) acc += sw[tid * 33 + k] * se[u * 32 + k];
                    g_part[(c * 96 + a) * H + tid] = acc;
                }
            }
        }
    } else if (b < 192 + nCombo) {
        int n = (b - 192) * 256 + tid;
        if (n < N) g_combo[n] = x[n] * 3 + s[n];
    } else {
        int idx = (b - 192 - nCombo) * 256 + tid;
        if (idx < H * H) {
            int n = idx >> 7, k = idx & 127;
            g_W3h[idx] = __float2half_rn(lin_w[(size_t)n * FEAT + (2 * H + 6) + k]);
        }
    }
}

// ---------------------------------------------------------------------------
// Prologue 2: combine -> fp16 tables (285 blocks); also resets tile counter
// ---------------------------------------------------------------------------
__global__ void prologue2(const float* __restrict__ spin_w, const float* __restrict__ spin_b,
                          const float* __restrict__ lin_w, const float* __restrict__ lin_b)
{
    const int b = blockIdx.x, n = threadIdx.x;
    if (b == 0 && n == 0) g_tileCtr = 0u;
    const int a = b / 3, sc = b % 3;
    float A = 0.f, B = 0.f;
#pragma unroll
    for (int c = 0; c < 4; c++) A += g_part[(c * 96 + a) * H + n];
#pragma unroll
    for (int c = 4; c < 8; c++) B += g_part[(c * 96 + a) * H + n];
    const float* wrow = lin_w + (size_t)n * FEAT;
    float sf0 = spin_w[0 * 3 + sc] + spin_b[0];
    float sf1 = spin_w[1 * 3 + sc] + spin_b[1];
    float sf2 = spin_w[2 * 3 + sc] + spin_b[2];
    g_AtabH[b * H + n] = __float2half_rn(A + wrow[128] * sf0 + wrow[129] * sf1 + wrow[130] * sf2 + lin_b[n]);
    g_BtabH[b * H + n] = __float2half_rn(B + wrow[259] * sf0 + wrow[260] * sf1 + wrow[261] * sf2);
}

// no-op launch-window shifter so ncu (-s 5 -c 1) lands on edge_kernel
__global__ void knock() {}

// ---------------------------------------------------------------------------
// Persistent edge kernel: ONE 512-thread CTA per SM (single B copy in smem,
// 158 KB L1D -> fp16 tables fully L1-resident). Warp-independent 32-edge x
// 128-col tiles, fp16 main accumulators, tensor-core A-gen, work stealing.
// dyn smem: sBh(34816) | sWst(16 * 2176 = 34816) = 69632 B
// ---------------------------------------------------------------------------
__global__ void __launch_bounds__(512, 1)
edge_kernel(const float* __restrict__ rbf,
            const int*   __restrict__ ii,
            const int*   __restrict__ jj,
            const float* __restrict__ rbf_w,
            const float* __restrict__ rbf_b,
            float*       __restrict__ out,
            int E)
{
    extern __shared__ __align__(16) char smem[];
    __half* sBh  = (__half*)(smem);
    __half* sWst = (__half*)(smem + 34816);

    const int tid = threadIdx.x, w = tid >> 5, lane = tid & 31;

    for (int idx = tid; idx < H * H; idx += 512) {
        int n = idx >> 7, k = idx & 127;
        sBh[n * LDR + k] = g_W3h[idx];
    }
    __syncthreads();

    const uint32_t bBase = smem_u32(sBh)
        + (uint32_t)((((lane >> 4) & 1) * 8 + (lane & 7)) * LDR + ((lane >> 3) & 1) * 8) * 2u;

    __half* swh_ = sWst + w * (8 * LDH);

    const int r0e = lane >> 2;
    const int c0 = (lane & 3) * 2;
    const int el = lane & 15;
    const int kd = c0;                 // rbf-dim pair for pre-MMA

    // ---- rbfW fragments for the pre-activation MMA, loaded ONCE.
    uint32_t bpre[8][2];
#pragma unroll
    for (int ks = 0; ks < 8; ks++)
#pragma unroll
        for (int g = 0; g < 2; g++) {
            int col = ks * 16 + g * 8 + r0e;
            float v0, v1;
            if (kd < RDIM) { v0 = rbf_w[col * RDIM + kd]; v1 = rbf_w[col * RDIM + kd + 1]; }
            else           { v0 = rbf_b[col];             v1 = 0.f; }
            bpre[ks][g] = pack2h(v0, v1);
        }

    const int ntiles = (E + 31) >> 5;

    // ---- grab + prefetch first 32-edge tile
    int t = grab_tile();
    uint32_t apre[2][2];               // [edge-half][edge-group]
    int myc0 = 0, myc1 = 0;
#pragma unroll
    for (int eh = 0; eh < 2; eh++) { apre[eh][0] = 0; apre[eh][1] = 0; }
    if (t < ntiles) {
        const int eb = t * 32;
#pragma unroll
        for (int eh = 0; eh < 2; eh++)
#pragma unroll
            for (int eg = 0; eg < 2; eg++) {
                if (kd < RDIM) {
                    float2 u = *(const float2*)(rbf + (size_t)min(eb + eh * 16 + eg * 8 + r0e, E - 1) * RDIM + kd);
                    apre[eh][eg] = pack2h(u.x, u.y);
                } else apre[eh][eg] = pack2h(1.f, 0.f);
            }
        int le0 = min(eb + el, E - 1);
        int le1 = min(eb + 16 + el, E - 1);
        myc0 = g_combo[(lane < 16) ? ii[le0] : jj[le0]];
        myc1 = g_combo[(lane < 16) ? ii[le1] : jj[le1]];
    }

    while (t < ntiles) {
        const int eb = t * 32;
        const int tn = grab_tile();    // latency hidden under this tile

        uint32_t cc[16][2][2];         // [n8-strip][edge-half][reg] fp16x2 acc
#pragma unroll
        for (int f = 0; f < 16; f++) {
            cc[f][0][0] = 0u; cc[f][0][1] = 0u;
            cc[f][1][0] = 0u; cc[f][1][1] = 0u;
        }

#pragma unroll
        for (int ks = 0; ks < 8; ks++) {
            // ---- A-frags for both edge halves via pre-MMA + f16x2 silu
            uint32_t a0[4], a1[4];
            {
                float p0[4] = {0.f,0.f,0.f,0.f}, p1[4] = {0.f,0.f,0.f,0.f};
                mma1688(p0, apre[0][0], apre[0][1], bpre[ks][0]);
                mma1688(p1, apre[0][0], apre[0][1], bpre[ks][1]);
                a0[0] = silu2h(p0[0], p0[1]);
                a0[1] = silu2h(p0[2], p0[3]);
                a0[2] = silu2h(p1[0], p1[1]);
                a0[3] = silu2h(p1[2], p1[3]);
            }
            {
                float p0[4] = {0.f,0.f,0.f,0.f}, p1[4] = {0.f,0.f,0.f,0.f};
                mma1688(p0, apre[1][0], apre[1][1], bpre[ks][0]);
                mma1688(p1, apre[1][0], apre[1][1], bpre[ks][1]);
                a1[0] = silu2h(p0[0], p0[1]);
                a1[1] = silu2h(p0[2], p0[3]);
                a1[2] = silu2h(p1[0], p1[1]);
                a1[3] = silu2h(p1[2], p1[3]);
            }

            const uint32_t koff = (uint32_t)ks * 32u;
#pragma unroll
            for (int fp = 0; fp < 8; fp++) {
                uint32_t bh[4];
                ldsm4(bh, bBase + (uint32_t)fp * (16u * LDR * 2u) + koff);
                mma16816h(cc[2 * fp][0],     a0, bh);
                mma16816h(cc[2 * fp + 1][0], a0, bh + 2);
                mma16816h(cc[2 * fp][1],     a1, bh);
                mma16816h(cc[2 * fp + 1][1], a1, bh + 2);
            }
        }

        // ---- prefetch next tile (epilogue hides it)
        uint32_t nap[2][2] = {{0u,0u},{0u,0u}};
        int nmyc0 = 0, nmyc1 = 0;
        if (tn < ntiles) {
            const int ebn = tn * 32;
#pragma unroll
            for (int eh = 0; eh < 2; eh++)
#pragma unroll
                for (int eg = 0; eg < 2; eg++) {
                    if (kd < RDIM) {
                        float2 u = *(const float2*)(rbf + (size_t)min(ebn + eh * 16 + eg * 8 + r0e, E - 1) * RDIM + kd);
                        nap[eh][eg] = pack2h(u.x, u.y);
                    } else nap[eh][eg] = pack2h(1.f, 0.f);
                }
            int le0 = min(ebn + el, E - 1);
            int le1 = min(ebn + 16 + el, E - 1);
            nmyc0 = g_combo[(lane < 16) ? ii[le0] : jj[le0]];
            nmyc1 = g_combo[(lane < 16) ? ii[le1] : jj[le1]];
        }

        // ---- epilogue: four 8-edge slabs through the per-warp staging slot
#pragma unroll
        for (int sh = 0; sh < 4; sh++) {
            const int eh = sh >> 1, rg = sh & 1;
            const int mycS = (sh < 2) ? myc0 : myc1;
#pragma unroll
            for (int f = 0; f < 16; f++) {
                // acc reg is already packed half2 (n-pair) — direct store
                *(uint32_t*)(swh_ + r0e * LDH + f * 8 + c0) = cc[f][eh][rg];
            }
            __syncwarp();
            const int colb = lane * 4;
            const int ebs = eb + sh * 8;
#pragma unroll
            for (int e = 0; e < 8; e++) {
                const int ge = ebs + e;
                const int me = (sh & 1) * 8 + e;   // index within this myc reg's 16 edges
                const int ci = __shfl_sync(0xffffffffu, mycS, me);
                const int cj = __shfl_sync(0xffffffffu, mycS, 16 + me);
                uint2 acr = *(const uint2*)(swh_ + e * LDH + colb);
                uint2 ar  = *(const uint2*)(g_AtabH + ci * H + colb);
                uint2 br  = *(const uint2*)(g_BtabH + cj * H + colb);
                __half2 s01 = __hadd2(__hadd2(*(__half2*)&acr.x, *(__half2*)&ar.x), *(__half2*)&br.x);
                __half2 s23 = __hadd2(__hadd2(*(__half2*)&acr.y, *(__half2*)&ar.y), *(__half2*)&br.y);
                float2 f01 = __half22float2(s01), f23 = __half22float2(s23);
                float4 o;
                o.x = fast_silu(f01.x);
                o.y = fast_silu(f01.y);
                o.z = fast_silu(f23.x);
                o.w = fast_silu(f23.y);
                if (ge < E) __stcs((float4*)(out + (size_t)ge * H + colb), o);
            }
            __syncwarp();
        }

        apre[0][0] = nap[0][0]; apre[0][1] = nap[0][1];
        apre[1][0] = nap[1][0]; apre[1][1] = nap[1][1];
        myc0 = nmyc0; myc1 = nmyc1;
        t = tn;
    }
}

// ---------------------------------------------------------------------------
extern "C" void kernel_launch(void* const* d_in, const int* in_sizes, int n_in,
                              void* d_out, int out_size)
{
    const int*   x      = (const int*)  d_in[0];
    const int*   s      = (const int*)  d_in[1];
    const float* rbf    = (const float*)d_in[2];
    const int*   ii     = (const int*)  d_in[3];
    const int*   jj     = (const int*)  d_in[4];
    const float* emb_w  = (const float*)d_in[5];
    const float* spin_w = (const float*)d_in[6];
    const float* spin_b = (const float*)d_in[7];
    const float* rbf_w  = (const float*)d_in[8];
    const float* rbf_b  = (const float*)d_in[9];
    const float* lin_w  = (const float*)d_in[10];
    const float* lin_b  = (const float*)d_in[11];
    float* out = (float*)d_out;

    int N    = in_sizes[0];
    int E    = in_sizes[3];
    int nEmb = in_sizes[5] / H;     // 95

    int nCombo = (N + 255) / 256;
    int nSplit = (H * H + 255) / 256;
    prologue1<<<192 + nCombo + nSplit, 256>>>(x, s, emb_w, lin_w, N, nCombo, nEmb);
    prologue2<<<285, 128>>>(spin_w, spin_b, lin_w, lin_b);
    knock<<<1, 32>>>();

    cudaFuncSetAttribute(edge_kernel, cudaFuncAttributeMaxDynamicSharedMemorySize, 69632);
    edge_kernel<<<NSM, 512, 69632>>>(rbf, ii, jj, rbf_w, rbf_b, out, E);
}